// round 16
// baseline (speedup 1.0000x reference)
#include <cuda_runtime.h>
#include <cuda_bf16.h>
#include <cstdint>

#define BB 64
#define FF 256
#define JJ 25
#define FILT 64
#define C1 128
#define NNODES (BB * FF * JJ)              // 409600
#define NE (NNODES * FILT)                 // 26214400
#define MTOT (BB * FF)                     // 16384
#define KCI 1600
#define EPSV 1e-5f

// ---------------------------------------------------------------------------
// Scratch
// ---------------------------------------------------------------------------
__device__ float g_z2[NE];                 // GCN2 pre-BN output [node][c]
__device__ __nv_bfloat16 g_zhi[NE];        // act(z2) bf16 hi
__device__ __nv_bfloat16 g_zlo[NE];        // act(z2) bf16 lo
__device__ __nv_bfloat16 g_wwhi[384 * KCI];// tap-split conv1 weights, bf16 hi
__device__ __nv_bfloat16 g_wwlo[384 * KCI];// bf16 lo residual
__device__ __nv_bfloat16 g_w2hb[FILT * FILT];
__device__ __nv_bfloat16 g_w2lb[FILT * FILT];
__device__ float g_w1out[BB * C1 * FF];    // conv1 raw output (pre-BN)
__device__ float g_v[BB * FILT * FF];      // conv2 raw output (pre-BN)
__device__ float g_p1[2 * 64 * 1024];
__device__ float g_p2[2 * 64 * 3200];
__device__ float g_pC1[2 * 128 * 128];
__device__ float g_pC2[2 * 64 * 256];
__device__ float g_scale1[64], g_shift1[64];
__device__ float g_scale2[64], g_shift2[64];

__device__ __forceinline__ float dinvf(int j) {
    return (j == 0 || j == JJ - 1) ? 0.70710678118654752f : 0.57735026918962576f;
}
__device__ __forceinline__ float lrelu(float v) { return v >= 0.f ? v : 0.2f * v; }

#define MMA_BF16(d, av, b0, b1) \
    asm volatile("mma.sync.aligned.m16n8k16.row.col.f32.bf16.bf16.f32 " \
        "{%0,%1,%2,%3}, {%4,%5,%6,%7}, {%8,%9}, {%0,%1,%2,%3};" \
        : "+f"((d)[0]), "+f"((d)[1]), "+f"((d)[2]), "+f"((d)[3]) \
        : "r"((av)[0]), "r"((av)[1]), "r"((av)[2]), "r"((av)[3]), \
          "r"(b0), "r"(b1))

__device__ __forceinline__ void cp_async16(uint32_t saddr, const void* g) {
    asm volatile("cp.async.cg.shared.global [%0], [%1], 16;" :: "r"(saddr), "l"(g) : "memory");
}

// ---------------------------------------------------------------------------
// K0: merged prep + gcn1 stats. (unchanged, passing)
// ---------------------------------------------------------------------------
__global__ __launch_bounds__(256) void prep_stats(
    const float* __restrict__ cw1, const float* __restrict__ W2,
    const float* __restrict__ x, const float* __restrict__ W1,
    const float* __restrict__ b1,
    __nv_bfloat16* __restrict__ whi, __nv_bfloat16* __restrict__ wlo,
    __nv_bfloat16* __restrict__ w2h, __nv_bfloat16* __restrict__ w2l,
    float* __restrict__ part) {
    int bid = blockIdx.x;
    int tid = threadIdx.x;
    if (bid < 2400) {
        int idx = bid * 256 + tid;                // < 614400 exactly
        int n = idx / KCI, ci = idx - n * KCI;
        int k = n >> 7, o = n & 127;
        float w = cw1[(size_t)o * 4800 + ci * 3 + k];
        __nv_bfloat16 hb = __float2bfloat16(w);
        whi[idx] = hb;
        wlo[idx] = __float2bfloat16(w - __bfloat162float(hb));
        return;
    }
    if (bid < 2416) {
        int i = (bid - 2400) * 256 + tid;         // < 4096
        int n = i >> 6, k = i & 63;
        float w = W2[k * 64 + n];
        __nv_bfloat16 hb = __float2bfloat16(w);
        w2h[i] = hb;
        w2l[i] = __float2bfloat16(w - __bfloat162float(hb));
        return;
    }
    int sb = bid - 2416;                          // 0..1023
    __shared__ float xs[1200], xef[1200], W1s[192], b1s[64], ss[256], qq[256];
    if (tid < 192) W1s[tid] = W1[tid];
    if (tid < 64) b1s[tid] = b1[tid];
    int base = sb * 1200;
    for (int i = tid; i < 1200; i += 256) xs[i] = x[base + i];
    __syncthreads();
    for (int i = tid; i < 400; i += 256) {
        int j = i % 25;
        float dj = dinvf(j);
        float cm = (j > 0) ? dinvf(j - 1) : 0.f;
        float cp = (j < 24) ? dinvf(j + 1) : 0.f;
        int im = (i > 0) ? i - 1 : 0, ip = (i < 399) ? i + 1 : 399;
#pragma unroll
        for (int d = 0; d < 3; d++)
            xef[i * 3 + d] = dj * (dj * xs[i * 3 + d] + cm * xs[im * 3 + d] + cp * xs[ip * 3 + d]);
    }
    __syncthreads();

    int c = tid & 63, sub = tid >> 6;
    float w0 = W1s[c], w1 = W1s[64 + c], w2 = W1s[128 + c], bb = b1s[c];
    float s = 0.f, q = 0.f;
    for (int it = 0; it < 100; it++) {
        int nl = it * 4 + sub;
        float z = xef[nl * 3] * w0 + xef[nl * 3 + 1] * w1 + xef[nl * 3 + 2] * w2 + bb;
        s += z; q += z * z;
    }
    ss[tid] = s; qq[tid] = q;
    __syncthreads();
    if (tid < 64) {
        s = ss[tid] + ss[tid + 64] + ss[tid + 128] + ss[tid + 192];
        q = qq[tid] + qq[tid + 64] + qq[tid + 128] + qq[tid + 192];
        part[tid * 1024 + sb] = s;
        part[65536 + tid * 1024 + sb] = q;
    }
}

// ---------------------------------------------------------------------------
// BN finalize (p1/p2 only): part S at [c*R + r], Q at [C*R + c*R + r].
// ---------------------------------------------------------------------------
__global__ __launch_bounds__(256) void bn_final(
    const float* __restrict__ part, int R, int C,
    const float* __restrict__ g, const float* __restrict__ be, float invN,
    float* __restrict__ scale, float* __restrict__ shift) {
    int c = blockIdx.x, tid = threadIdx.x;
    __shared__ float ss[256], qq[256];
    const float* pS = part + (size_t)c * R;
    const float* pQ = part + (size_t)C * R + (size_t)c * R;
    float s = 0.f, q = 0.f;
    for (int r = tid; r < R; r += 256) { s += pS[r]; q += pQ[r]; }
    ss[tid] = s; qq[tid] = q;
    __syncthreads();
    for (int o = 128; o > 0; o >>= 1) {
        if (tid < o) { ss[tid] += ss[tid + o]; qq[tid] += qq[tid + o]; }
        __syncthreads();
    }
    if (tid == 0) {
        float m = ss[0] * invN;
        float var = qq[0] * invN - m * m;
        float rstd = rsqrtf(var + EPSV);
        float sc = g[c] * rstd;
        scale[c] = sc;
        shift[c] = be[c] - m * sc;
    }
}

// ---------------------------------------------------------------------------
// K2: gcn2 via bf16x3 MMA (unchanged, passing).
// ---------------------------------------------------------------------------
#define G2S 72
#define G2_BYTES 55296

__global__ __launch_bounds__(256) void gcn2_mma(
    const float* __restrict__ x, const float* __restrict__ W1,
    const float* __restrict__ b1, const float* __restrict__ sc1,
    const float* __restrict__ sh1, const __nv_bfloat16* __restrict__ w2hb,
    const __nv_bfloat16* __restrict__ w2lb, const float* __restrict__ b2,
    float* __restrict__ part, float* __restrict__ z2b) {
    extern __shared__ __align__(16) char dynraw[];
    __nv_bfloat16* Ahi = reinterpret_cast<__nv_bfloat16*>(dynraw);
    __nv_bfloat16* Alo = reinterpret_cast<__nv_bfloat16*>(dynraw + 18432);
    __nv_bfloat16* Bhi = reinterpret_cast<__nv_bfloat16*>(dynraw + 36864);
    __nv_bfloat16* Blo = reinterpret_cast<__nv_bfloat16*>(dynraw + 46080);
    __shared__ __align__(16) float xs[396], xef[520];
    __shared__ __align__(16) float W1s[192], b1s[64], sc1s[64], sh1s[64], b2s[64];
    __shared__ float redS[256], redQ[256];

    int tid = threadIdx.x, lane = tid & 31, wid = tid >> 5;
    int n0 = blockIdx.x * 128;

    if (tid < 192) W1s[tid] = W1[tid];
    if (tid < 64) {
        b1s[tid] = b1[tid]; sc1s[tid] = sc1[tid];
        sh1s[tid] = sh1[tid]; b2s[tid] = b2[tid];
    }
    for (int i = tid; i < 396; i += 256) {
        int gi = (n0 - 2) * 3 + i;
        xs[i] = (gi >= 0 && gi < NNODES * 3) ? x[gi] : 0.f;
    }
    for (int i = tid; i < 2048; i += 256) {
        int n = i >> 5, kk = i & 31;
        *reinterpret_cast<uint32_t*>(Bhi + n * G2S + kk * 2) =
            *reinterpret_cast<const uint32_t*>(w2hb + n * 64 + kk * 2);
        *reinterpret_cast<uint32_t*>(Blo + n * G2S + kk * 2) =
            *reinterpret_cast<const uint32_t*>(w2lb + n * 64 + kk * 2);
    }
    __syncthreads();

    for (int i = tid; i < 130; i += 256) {
        int m = n0 - 1 + i;
        float e0 = 0.f, e1 = 0.f, e2 = 0.f;
        if (m >= 0 && m < NNODES) {
            int j = m % 25;
            float dj = dinvf(j);
            float cm = (j > 0) ? dinvf(j - 1) : 0.f;
            float cp = (j < 24) ? dinvf(j + 1) : 0.f;
            const float* xc = xs + (i + 1) * 3;
            e0 = dj * (dj * xc[0] + cm * xc[-3] + cp * xc[3]);
            e1 = dj * (dj * xc[1] + cm * xc[-2] + cp * xc[4]);
            e2 = dj * (dj * xc[2] + cm * xc[-1] + cp * xc[5]);
        }
        xef[i * 4] = e0; xef[i * 4 + 1] = e1; xef[i * 4 + 2] = e2;
    }
    __syncthreads();

    {
        const float4* W1s4 = reinterpret_cast<const float4*>(W1s);
        const float4* b4 = reinterpret_cast<const float4*>(b1s);
        const float4* sc4 = reinterpret_cast<const float4*>(sc1s);
        const float4* sh4 = reinterpret_cast<const float4*>(sh1s);
        for (int i = tid; i < 2048; i += 256) {
            int cg = i & 15, nl = i >> 4;
            int m = n0 + nl, j = m % 25;
            float dj = dinvf(j);
            float cm = (j > 0) ? dinvf(j - 1) : 0.f;
            float cp = (j < 24) ? dinvf(j + 1) : 0.f;
            float4 w0 = W1s4[cg], w1 = W1s4[16 + cg], w2 = W1s4[32 + cg];
            float4 bb = b4[cg], sv = sc4[cg], hs = sh4[cg];
            float4 h[3];
#pragma unroll
            for (int d = 0; d < 3; d++) {
                float e0 = xef[(nl + d) * 4], e1 = xef[(nl + d) * 4 + 1],
                      e2 = xef[(nl + d) * 4 + 2];
                float4 z;
                z.x = e0 * w0.x + e1 * w1.x + e2 * w2.x + bb.x;
                z.y = e0 * w0.y + e1 * w1.y + e2 * w2.y + bb.y;
                z.z = e0 * w0.z + e1 * w1.z + e2 * w2.z + bb.z;
                z.w = e0 * w0.w + e1 * w1.w + e2 * w2.w + bb.w;
                h[d].x = lrelu(fmaf(z.x, sv.x, hs.x));
                h[d].y = lrelu(fmaf(z.y, sv.y, hs.y));
                h[d].z = lrelu(fmaf(z.z, sv.z, hs.z));
                h[d].w = lrelu(fmaf(z.w, sv.w, hs.w));
            }
            float4 v;
            v.x = dj * (dj * h[1].x + cm * h[0].x + cp * h[2].x);
            v.y = dj * (dj * h[1].y + cm * h[0].y + cp * h[2].y);
            v.z = dj * (dj * h[1].z + cm * h[0].z + cp * h[2].z);
            v.w = dj * (dj * h[1].w + cm * h[0].w + cp * h[2].w);
            __nv_bfloat16 hx = __float2bfloat16(v.x), hy = __float2bfloat16(v.y);
            __nv_bfloat16 hz = __float2bfloat16(v.z), hw = __float2bfloat16(v.w);
            __nv_bfloat16 lx = __float2bfloat16(v.x - __bfloat162float(hx));
            __nv_bfloat16 ly = __float2bfloat16(v.y - __bfloat162float(hy));
            __nv_bfloat16 lz = __float2bfloat16(v.z - __bfloat162float(hz));
            __nv_bfloat16 lw = __float2bfloat16(v.w - __bfloat162float(hw));
            int di = nl * G2S + cg * 4;
            *reinterpret_cast<__nv_bfloat162*>(Ahi + di)     = __halves2bfloat162(hx, hy);
            *reinterpret_cast<__nv_bfloat162*>(Ahi + di + 2) = __halves2bfloat162(hz, hw);
            *reinterpret_cast<__nv_bfloat162*>(Alo + di)     = __halves2bfloat162(lx, ly);
            *reinterpret_cast<__nv_bfloat162*>(Alo + di + 2) = __halves2bfloat162(lz, lw);
        }
    }
    __syncthreads();

    int wm = wid & 3, wn = wid >> 2;
    float acc[2][4][4];
#pragma unroll
    for (int mt = 0; mt < 2; mt++)
#pragma unroll
        for (int nt = 0; nt < 4; nt++)
#pragma unroll
            for (int u = 0; u < 4; u++) acc[mt][nt][u] = 0.f;

#pragma unroll
    for (int kt = 0; kt < 4; kt++) {
        uint32_t ahi[2][4], alo[2][4], bhi[4][2], blo[4][2];
        int abase = (wm * 32 + (lane >> 2)) * G2S + (lane & 3) * 2 + kt * 16;
#pragma unroll
        for (int mt = 0; mt < 2; mt++) {
            int o = abase + mt * 16 * G2S;
            ahi[mt][0] = *reinterpret_cast<const uint32_t*>(Ahi + o);
            ahi[mt][1] = *reinterpret_cast<const uint32_t*>(Ahi + o + 8 * G2S);
            ahi[mt][2] = *reinterpret_cast<const uint32_t*>(Ahi + o + 8);
            ahi[mt][3] = *reinterpret_cast<const uint32_t*>(Ahi + o + 8 * G2S + 8);
            alo[mt][0] = *reinterpret_cast<const uint32_t*>(Alo + o);
            alo[mt][1] = *reinterpret_cast<const uint32_t*>(Alo + o + 8 * G2S);
            alo[mt][2] = *reinterpret_cast<const uint32_t*>(Alo + o + 8);
            alo[mt][3] = *reinterpret_cast<const uint32_t*>(Alo + o + 8 * G2S + 8);
        }
        int bbase = (wn * 32 + (lane >> 2)) * G2S + (lane & 3) * 2 + kt * 16;
#pragma unroll
        for (int nt = 0; nt < 4; nt++) {
            int o = bbase + nt * 8 * G2S;
            bhi[nt][0] = *reinterpret_cast<const uint32_t*>(Bhi + o);
            bhi[nt][1] = *reinterpret_cast<const uint32_t*>(Bhi + o + 8);
            blo[nt][0] = *reinterpret_cast<const uint32_t*>(Blo + o);
            blo[nt][1] = *reinterpret_cast<const uint32_t*>(Blo + o + 8);
        }
#pragma unroll
        for (int nt = 0; nt < 4; nt++) {
            MMA_BF16(acc[0][nt], ahi[0], bhi[nt][0], bhi[nt][1]);
            MMA_BF16(acc[1][nt], ahi[1], bhi[nt][0], bhi[nt][1]);
        }
#pragma unroll
        for (int nt = 0; nt < 4; nt++) {
            MMA_BF16(acc[0][nt], ahi[0], blo[nt][0], blo[nt][1]);
            MMA_BF16(acc[1][nt], ahi[1], blo[nt][0], blo[nt][1]);
        }
#pragma unroll
        for (int nt = 0; nt < 4; nt++) {
            MMA_BF16(acc[0][nt], alo[0], bhi[nt][0], bhi[nt][1]);
            MMA_BF16(acc[1][nt], alo[1], bhi[nt][0], bhi[nt][1]);
        }
    }

#pragma unroll
    for (int nt = 0; nt < 4; nt++) {
        int c0 = wn * 32 + nt * 8 + ((lane & 3) << 1);
        float bb0 = b2s[c0], bb1 = b2s[c0 + 1];
        float s0 = 0.f, q0 = 0.f, s1 = 0.f, q1 = 0.f;
#pragma unroll
        for (int mt = 0; mt < 2; mt++) {
            int row = n0 + wm * 32 + mt * 16 + (lane >> 2);
            float u0 = acc[mt][nt][0] + bb0, u1 = acc[mt][nt][1] + bb1;
            float u2 = acc[mt][nt][2] + bb0, u3 = acc[mt][nt][3] + bb1;
            *reinterpret_cast<float2*>(z2b + (size_t)row * 64 + c0) = make_float2(u0, u1);
            *reinterpret_cast<float2*>(z2b + (size_t)(row + 8) * 64 + c0) = make_float2(u2, u3);
            s0 += u0 + u2; q0 += u0 * u0 + u2 * u2;
            s1 += u1 + u3; q1 += u1 * u1 + u3 * u3;
        }
#pragma unroll
        for (int o = 4; o < 32; o <<= 1) {
            s0 += __shfl_xor_sync(0xffffffffu, s0, o);
            q0 += __shfl_xor_sync(0xffffffffu, q0, o);
            s1 += __shfl_xor_sync(0xffffffffu, s1, o);
            q1 += __shfl_xor_sync(0xffffffffu, q1, o);
        }
        if (lane < 4) {
            redS[c0 * 4 + wm] = s0; redS[(c0 + 1) * 4 + wm] = s1;
            redQ[c0 * 4 + wm] = q0; redQ[(c0 + 1) * 4 + wm] = q1;
        }
    }
    __syncthreads();
    if (tid < 64) {
        float S = redS[tid * 4] + redS[tid * 4 + 1] + redS[tid * 4 + 2] + redS[tid * 4 + 3];
        float Q = redQ[tid * 4] + redQ[tid * 4 + 1] + redQ[tid * 4 + 2] + redQ[tid * 4 + 3];
        part[tid * 3200 + blockIdx.x] = S;
        part[204800 + tid * 3200 + blockIdx.x] = Q;
    }
}

// ---------------------------------------------------------------------------
// K2b: z2 convert — BN2+LReLU+bf16 split. (unchanged)
// ---------------------------------------------------------------------------
__global__ __launch_bounds__(256) void z2convert(
    const float* __restrict__ z2, const float* __restrict__ sc,
    const float* __restrict__ sh, __nv_bfloat16* __restrict__ zhi,
    __nv_bfloat16* __restrict__ zlo) {
    __shared__ float scs[64], shs[64];
    int tid = threadIdx.x;
    if (tid < 64) { scs[tid] = sc[tid]; shs[tid] = sh[tid]; }
    __syncthreads();
    size_t base = (size_t)blockIdx.x * 1024 + tid * 4;
    int c = (tid * 4) & 63;
    float4 v = *reinterpret_cast<const float4*>(z2 + base);
    v.x = lrelu(fmaf(v.x, scs[c],     shs[c]));
    v.y = lrelu(fmaf(v.y, scs[c + 1], shs[c + 1]));
    v.z = lrelu(fmaf(v.z, scs[c + 2], shs[c + 2]));
    v.w = lrelu(fmaf(v.w, scs[c + 3], shs[c + 3]));
    __nv_bfloat16 hx = __float2bfloat16(v.x), hy = __float2bfloat16(v.y);
    __nv_bfloat16 hz = __float2bfloat16(v.z), hw = __float2bfloat16(v.w);
    __nv_bfloat16 lx = __float2bfloat16(v.x - __bfloat162float(hx));
    __nv_bfloat16 ly = __float2bfloat16(v.y - __bfloat162float(hy));
    __nv_bfloat16 lz = __float2bfloat16(v.z - __bfloat162float(hz));
    __nv_bfloat16 lw = __float2bfloat16(v.w - __bfloat162float(hw));
    *reinterpret_cast<__nv_bfloat162*>(zhi + base)     = __halves2bfloat162(hx, hy);
    *reinterpret_cast<__nv_bfloat162*>(zhi + base + 2) = __halves2bfloat162(hz, hw);
    *reinterpret_cast<__nv_bfloat162*>(zlo + base)     = __halves2bfloat162(lx, ly);
    *reinterpret_cast<__nv_bfloat162*>(zlo + base + 2) = __halves2bfloat162(lz, lw);
}

// ---------------------------------------------------------------------------
// K3: conv1 fused with shift-add (unchanged, passing).
// ---------------------------------------------------------------------------
#define AROWS 5200                                  // 130*40 bf16
#define BROWS 15360                                 // 384*40 bf16
#define STAGEE (2 * AROWS + 2 * BROWS)
#define CF_BYTES (2 * STAGEE * 2)                   // 164480

__global__ __launch_bounds__(256) void conv1_fused(
    const __nv_bfloat16* __restrict__ zhi, const __nv_bfloat16* __restrict__ zlo,
    const __nv_bfloat16* __restrict__ wwhi, const __nv_bfloat16* __restrict__ wwlo,
    const float* __restrict__ cb1, float* __restrict__ w1o,
    float* __restrict__ part) {
    extern __shared__ __align__(16) char dynraw[];
    __nv_bfloat16* sm = reinterpret_cast<__nv_bfloat16*>(dynraw);
    int tid = threadIdx.x, lane = tid & 31, wid = tid >> 5;
    int wm = wid & 3, wn = wid >> 2;
    int m0 = blockIdx.x * 128;
    int bidx = m0 >> 8;
    int f0g = m0 & 255;
    int zr = (f0g == 0) ? 0 : 129;
    int mA0 = m0 - 1;

    float acc[2][8][4];
#pragma unroll
    for (int mt = 0; mt < 2; mt++)
#pragma unroll
        for (int nt = 0; nt < 8; nt++)
#pragma unroll
            for (int u = 0; u < 4; u++) acc[mt][nt][u] = 0.f;

#define LOADAB(bufi, step) do { \
        int ci0_ = (step) * 32; \
        __nv_bfloat16* Ah_ = sm + (bufi) * STAGEE; \
        __nv_bfloat16* Al_ = Ah_ + AROWS; \
        __nv_bfloat16* Bh_ = Al_ + AROWS; \
        __nv_bfloat16* Bl_ = Bh_ + BROWS; \
        if (tid < 16) { \
            __nv_bfloat16* zd = (tid < 8 ? Ah_ : Al_) + zr * 40 + (tid & 7) * 4; \
            *reinterpret_cast<float2*>(zd) = make_float2(0.f, 0.f); \
        } \
        _Pragma("unroll") \
        for (int u = 0; u < 5; u++) { \
            int fi = u * 256 + tid; \
            if (fi < 1040) { \
                int sel = fi >= 520; \
                int rem = sel ? fi - 520 : fi; \
                int row = rem >> 2, gg = rem & 3; \
                if (row != zr) { \
                    const __nv_bfloat16* src = (sel ? zlo : zhi) + \
                        (size_t)(mA0 + row) * KCI + ci0_ + gg * 8; \
                    __nv_bfloat16* dst = (sel ? Al_ : Ah_) + row * 40 + gg * 8; \
                    cp_async16((uint32_t)__cvta_generic_to_shared(dst), src); \
                } \
            } \
        } \
        _Pragma("unroll") \
        for (int u = 0; u < 12; u++) { \
            int fi = u * 256 + tid; \
            int sel = fi >= 1536; \
            int rem = sel ? fi - 1536 : fi; \
            int row = rem >> 2, gg = rem & 3; \
            const __nv_bfloat16* src = (sel ? wwlo : wwhi) + \
                (size_t)row * KCI + ci0_ + gg * 8; \
            __nv_bfloat16* dst = (sel ? Bl_ : Bh_) + row * 40 + gg * 8; \
            cp_async16((uint32_t)__cvta_generic_to_shared(dst), src); \
        } \
        asm volatile("cp.async.commit_group;" ::: "memory"); \
    } while (0)

    LOADAB(0, 0);

    for (int i = 0; i < 50; i++) {
        int buf = i & 1;
        asm volatile("cp.async.wait_group 0;" ::: "memory");
        __syncthreads();
        if (i < 49) LOADAB(buf ^ 1, i + 1);

        const __nv_bfloat16* Ah = sm + buf * STAGEE;
        const __nv_bfloat16* Al = Ah + AROWS;
        const __nv_bfloat16* Bh = Al + AROWS;
        const __nv_bfloat16* Bl = Bh + BROWS;
#pragma unroll
        for (int kt = 0; kt < 2; kt++) {
#pragma unroll
            for (int tap = 0; tap < 3; tap++) {
                uint32_t ahi[2][4], alo[2][4], bhi[8][2], blo[8][2];
                int abase = (wm * 32 + tap + (lane >> 2)) * 40 + (lane & 3) * 2 + kt * 16;
#pragma unroll
                for (int mt = 0; mt < 2; mt++) {
                    int o = abase + mt * 640;
                    ahi[mt][0] = *reinterpret_cast<const uint32_t*>(Ah + o);
                    ahi[mt][1] = *reinterpret_cast<const uint32_t*>(Ah + o + 320);
                    ahi[mt][2] = *reinterpret_cast<const uint32_t*>(Ah + o + 8);
                    ahi[mt][3] = *reinterpret_cast<const uint32_t*>(Ah + o + 328);
                    alo[mt][0] = *reinterpret_cast<const uint32_t*>(Al + o);
                    alo[mt][1] = *reinterpret_cast<const uint32_t*>(Al + o + 320);
                    alo[mt][2] = *reinterpret_cast<const uint32_t*>(Al + o + 8);
                    alo[mt][3] = *reinterpret_cast<const uint32_t*>(Al + o + 328);
                }
                int bbase = (tap * 128 + wn * 64 + (lane >> 2)) * 40 + (lane & 3) * 2 + kt * 16;
#pragma unroll
                for (int nt = 0; nt < 8; nt++) {
                    int o = bbase + nt * 320;
                    bhi[nt][0] = *reinterpret_cast<const uint32_t*>(Bh + o);
                    bhi[nt][1] = *reinterpret_cast<const uint32_t*>(Bh + o + 8);
                    blo[nt][0] = *reinterpret_cast<const uint32_t*>(Bl + o);
                    blo[nt][1] = *reinterpret_cast<const uint32_t*>(Bl + o + 8);
                }
#pragma unroll
                for (int nt = 0; nt < 8; nt++) {
                    MMA_BF16(acc[0][nt], ahi[0], bhi[nt][0], bhi[nt][1]);
                    MMA_BF16(acc[1][nt], ahi[1], bhi[nt][0], bhi[nt][1]);
                }
#pragma unroll
                for (int nt = 0; nt < 8; nt++) {
                    MMA_BF16(acc[0][nt], ahi[0], blo[nt][0], blo[nt][1]);
                    MMA_BF16(acc[1][nt], ahi[1], blo[nt][0], blo[nt][1]);
                }
#pragma unroll
                for (int nt = 0; nt < 8; nt++) {
                    MMA_BF16(acc[0][nt], alo[0], bhi[nt][0], bhi[nt][1]);
                    MMA_BF16(acc[1][nt], alo[1], bhi[nt][0], bhi[nt][1]);
                }
            }
        }
    }

    __syncthreads();
    float* T = reinterpret_cast<float*>(sm);         // 128 x 132
#pragma unroll
    for (int mt = 0; mt < 2; mt++)
#pragma unroll
        for (int nt = 0; nt < 8; nt++)
#pragma unroll
            for (int u = 0; u < 4; u++) {
                int fo = wm * 32 + mt * 16 + (lane >> 2) + ((u >> 1) ? 8 : 0);
                int o = wn * 64 + nt * 8 + ((lane & 3) << 1) + (u & 1);
                T[o * 132 + fo] = acc[mt][nt][u] + __ldg(cb1 + o);
            }
    __syncthreads();
    for (int i = tid; i < 4096; i += 256) {
        int o = i >> 5, f4 = i & 31;
        float4 v = *reinterpret_cast<const float4*>(T + o * 132 + f4 * 4);
        *reinterpret_cast<float4*>(
            w1o + (size_t)(bidx * 128 + o) * 256 + f0g + f4 * 4) = v;
    }
    if (tid < 128) {
        float S = 0.f, Q = 0.f;
#pragma unroll 8
        for (int k = 0; k < 128; k++) {
            float v = T[tid * 132 + k];
            S += v; Q += v * v;
        }
        part[tid * 128 + blockIdx.x] = S;
        part[16384 + tid * 128 + blockIdx.x] = Q;
    }
#undef LOADAB
}

// ---------------------------------------------------------------------------
// K6: Conv2 (1x1, 128->64) — now self-finalizes BN-C1 from partials.
// pC1 layout: S at [c*128 + r], Q at 16384 + [c*128 + r], R=128.
// ---------------------------------------------------------------------------
__global__ __launch_bounds__(256) void conv2_kernel(
    const float* __restrict__ w1o, const float* __restrict__ cw2,
    const float* __restrict__ cb2, const float* __restrict__ pC1,
    const float* __restrict__ cg1, const float* __restrict__ cbe1,
    float invN, float* __restrict__ vout, float* __restrict__ part) {
    __shared__ __align__(16) float Us[64 * 64];
    __shared__ __align__(16) float Ws2[64 * 64];
    __shared__ float scs[128], shs[128], sred[256], qred[256];
    int tid = threadIdx.x;
    int b = blockIdx.y;
    int f0 = blockIdx.x * 64;
    int fth = tid & 15, oth = tid >> 4;

    // inline BN-C1 finalize (deterministic redundant reduction, L2-resident)
    {
        int c = tid >> 1, hh = tid & 1;
        const float* pS = pC1 + c * 128 + hh * 64;
        const float* pQ = pC1 + 16384 + c * 128 + hh * 64;
        float s = 0.f, q = 0.f;
#pragma unroll 8
        for (int k = 0; k < 64; k++) { s += pS[k]; q += pQ[k]; }
        sred[tid] = s; qred[tid] = q;
    }
    __syncthreads();
    if (tid < 128) {
        float S = sred[2 * tid] + sred[2 * tid + 1];
        float Q = qred[2 * tid] + qred[2 * tid + 1];
        float m = S * invN;
        float var = Q * invN - m * m;
        float rstd = rsqrtf(var + EPSV);
        float sc = cg1[tid] * rstd;
        scs[tid] = sc;
        shs[tid] = cbe1[tid] - m * sc;
    }
    __syncthreads();

    float acc[4][4] = {};
    for (int ci0 = 0; ci0 < 128; ci0 += 64) {
        for (int i = tid; i < 4096; i += 256) {
            int cc = i >> 6, ffi = i & 63;
            float raw = w1o[(size_t)(b * 128 + ci0 + cc) * 256 + f0 + ffi];
            float v = fmaf(raw, scs[ci0 + cc], shs[ci0 + cc]);
            Us[i] = lrelu(v);
        }
        for (int i = tid; i < 4096; i += 256) {
            int o = i & 63, cc = i >> 6;
            Ws2[cc * 64 + o] = cw2[o * 128 + ci0 + cc];
        }
        __syncthreads();
#pragma unroll 8
        for (int cc = 0; cc < 64; cc++) {
            float4 iv = *reinterpret_cast<const float4*>(Us + cc * 64 + fth * 4);
            float4 wv = *reinterpret_cast<const float4*>(Ws2 + cc * 64 + oth * 4);
            acc[0][0] = fmaf(wv.x, iv.x, acc[0][0]); acc[0][1] = fmaf(wv.x, iv.y, acc[0][1]);
            acc[0][2] = fmaf(wv.x, iv.z, acc[0][2]); acc[0][3] = fmaf(wv.x, iv.w, acc[0][3]);
            acc[1][0] = fmaf(wv.y, iv.x, acc[1][0]); acc[1][1] = fmaf(wv.y, iv.y, acc[1][1]);
            acc[1][2] = fmaf(wv.y, iv.z, acc[1][2]); acc[1][3] = fmaf(wv.y, iv.w, acc[1][3]);
            acc[2][0] = fmaf(wv.z, iv.x, acc[2][0]); acc[2][1] = fmaf(wv.z, iv.y, acc[2][1]);
            acc[2][2] = fmaf(wv.z, iv.z, acc[2][2]); acc[2][3] = fmaf(wv.z, iv.w, acc[2][3]);
            acc[3][0] = fmaf(wv.w, iv.x, acc[3][0]); acc[3][1] = fmaf(wv.w, iv.y, acc[3][1]);
            acc[3][2] = fmaf(wv.w, iv.z, acc[3][2]); acc[3][3] = fmaf(wv.w, iv.w, acc[3][3]);
        }
        __syncthreads();
    }

    float* reds = Us;
    float* redq = Ws2;
#pragma unroll
    for (int i = 0; i < 4; i++) {
        int o = oth * 4 + i;
        float bias = __ldg(cb2 + o);
        float s = 0.f, q = 0.f;
#pragma unroll
        for (int j2 = 0; j2 < 4; j2++) {
            float r = acc[i][j2] + bias;
            vout[(size_t)(b * 64 + o) * 256 + f0 + fth * 4 + j2] = r;
            s += r; q += r * r;
        }
        reds[o * 17 + fth] = s;
        redq[o * 17 + fth] = q;
    }
    __syncthreads();
    if (tid < 64) {
        float S = 0.f, Q = 0.f;
#pragma unroll
        for (int t = 0; t < 16; t++) { S += reds[tid * 17 + t]; Q += redq[tid * 17 + t]; }
        int blk = blockIdx.y * 4 + blockIdx.x;
        part[tid * 256 + blk] = S;
        part[16384 + tid * 256 + blk] = Q;
    }
}

// ---------------------------------------------------------------------------
// K7: final — self-finalizes BN-C2 from partials, then BN+LReLU+transpose.
// pC2 layout: S at [c*256 + r], Q at 16384 + [c*256 + r], R=256.
// ---------------------------------------------------------------------------
__global__ __launch_bounds__(256) void final_kernel(
    const float* __restrict__ v, const float* __restrict__ pC2,
    const float* __restrict__ cg2, const float* __restrict__ cbe2,
    float invN, float* __restrict__ out) {
    __shared__ float s[64 * 65];
    __shared__ float scs[64], shs[64], sred[256], qred[256];
    int tid = threadIdx.x;
    int b = blockIdx.y;
    int f0 = blockIdx.x * 64;

    {
        int c = tid >> 2, qq4 = tid & 3;
        const float* pS = pC2 + c * 256 + qq4 * 64;
        const float* pQ = pC2 + 16384 + c * 256 + qq4 * 64;
        float sa = 0.f, qa = 0.f;
#pragma unroll 8
        for (int k = 0; k < 64; k++) { sa += pS[k]; qa += pQ[k]; }
        sred[tid] = sa; qred[tid] = qa;
    }
    __syncthreads();
    if (tid < 64) {
        float S = sred[4 * tid] + sred[4 * tid + 1] + sred[4 * tid + 2] + sred[4 * tid + 3];
        float Q = qred[4 * tid] + qred[4 * tid + 1] + qred[4 * tid + 2] + qred[4 * tid + 3];
        float m = S * invN;
        float var = Q * invN - m * m;
        float rstd = rsqrtf(var + EPSV);
        float sc = cg2[tid] * rstd;
        scs[tid] = sc;
        shs[tid] = cbe2[tid] - m * sc;
    }
    __syncthreads();

    for (int i = tid; i < 4096; i += 256) {
        int o = i >> 6, ffi = i & 63;
        s[o * 65 + ffi] = v[(size_t)(b * 64 + o) * 256 + f0 + ffi];
    }
    __syncthreads();
    for (int i = tid; i < 4096; i += 256) {
        int ffi = i >> 6, o = i & 63;
        float val = fmaf(s[o * 65 + ffi], scs[o], shs[o]);
        out[(size_t)(b * 256 + f0 + ffi) * 64 + o] = lrelu(val);
    }
}

// ---------------------------------------------------------------------------
// Launch
// ---------------------------------------------------------------------------
extern "C" void kernel_launch(void* const* d_in, const int* in_sizes, int n_in,
                              void* d_out, int out_size) {
    const float* x   = (const float*)d_in[0];
    const float* W1  = (const float*)d_in[4];
    const float* b1  = (const float*)d_in[5];
    const float* g1  = (const float*)d_in[6];
    const float* be1 = (const float*)d_in[7];
    const float* W2  = (const float*)d_in[8];
    const float* b2  = (const float*)d_in[9];
    const float* g2  = (const float*)d_in[10];
    const float* be2 = (const float*)d_in[11];
    const float* cw1 = (const float*)d_in[12];
    const float* cb1 = (const float*)d_in[13];
    const float* cg1 = (const float*)d_in[14];
    const float* cbe1= (const float*)d_in[15];
    const float* cw2 = (const float*)d_in[16];
    const float* cb2 = (const float*)d_in[17];
    const float* cg2 = (const float*)d_in[18];
    const float* cbe2= (const float*)d_in[19];
    float* out = (float*)d_out;

    float *z2, *w1o, *v, *p1, *p2, *pC1, *pC2;
    __nv_bfloat16 *zhi, *zlo, *whi, *wlo, *w2h, *w2l;
    float *s1, *h1, *s2, *h2;
    cudaGetSymbolAddress((void**)&z2,  g_z2);
    cudaGetSymbolAddress((void**)&zhi, g_zhi);
    cudaGetSymbolAddress((void**)&zlo, g_zlo);
    cudaGetSymbolAddress((void**)&whi, g_wwhi);
    cudaGetSymbolAddress((void**)&wlo, g_wwlo);
    cudaGetSymbolAddress((void**)&w2h, g_w2hb);
    cudaGetSymbolAddress((void**)&w2l, g_w2lb);
    cudaGetSymbolAddress((void**)&w1o, g_w1out);
    cudaGetSymbolAddress((void**)&v,   g_v);
    cudaGetSymbolAddress((void**)&p1,  g_p1);
    cudaGetSymbolAddress((void**)&p2,  g_p2);
    cudaGetSymbolAddress((void**)&pC1, g_pC1);
    cudaGetSymbolAddress((void**)&pC2, g_pC2);
    cudaGetSymbolAddress((void**)&s1,  g_scale1);
    cudaGetSymbolAddress((void**)&h1,  g_shift1);
    cudaGetSymbolAddress((void**)&s2,  g_scale2);
    cudaGetSymbolAddress((void**)&h2,  g_shift2);

    cudaFuncSetAttribute(conv1_fused, cudaFuncAttributeMaxDynamicSharedMemorySize, CF_BYTES);
    cudaFuncSetAttribute(gcn2_mma,   cudaFuncAttributeMaxDynamicSharedMemorySize, G2_BYTES);

    const float invN_nodes = 1.f / (float)NNODES;
    const float invN_bf    = 1.f / (float)(BB * FF);

    prep_stats<<<3440, 256>>>(cw1, W2, x, W1, b1, whi, wlo, w2h, w2l, p1);     // 0
    bn_final<<<64, 256>>>(p1, 1024, 64, g1, be1, invN_nodes, s1, h1);          // 1
    gcn2_mma<<<3200, 256, G2_BYTES>>>(x, W1, b1, s1, h1, w2h, w2l, b2, p2, z2);// 2
    bn_final<<<64, 256>>>(p2, 3200, 64, g2, be2, invN_nodes, s2, h2);          // 3
    z2convert<<<25600, 256>>>(z2, s2, h2, zhi, zlo);                           // 4
    conv1_fused<<<128, 256, CF_BYTES>>>(zhi, zlo, whi, wlo, cb1, w1o, pC1);    // 5
    conv2_kernel<<<dim3(4, BB), 256>>>(w1o, cw2, cb2, pC1, cg1, cbe1,
                                       invN_bf, v, pC2);                       // 6
    final_kernel<<<dim3(4, BB), 256>>>(v, pC2, cg2, cbe2, invN_bf, out);       // 7
}

// round 17
// speedup vs baseline: 1.1701x; 1.1701x over previous
#include <cuda_runtime.h>
#include <cuda_bf16.h>
#include <cstdint>

#define BB 64
#define FF 256
#define JJ 25
#define FILT 64
#define C1 128
#define NNODES (BB * FF * JJ)              // 409600
#define NE (NNODES * FILT)                 // 26214400
#define MTOT (BB * FF)                     // 16384
#define KCI 1600
#define EPSV 1e-5f

// ---------------------------------------------------------------------------
// Scratch
// ---------------------------------------------------------------------------
__device__ float g_z2[NE];                 // GCN2 pre-BN output [node][c]
__device__ __nv_bfloat16 g_zhi[NE];        // act(z2) bf16 hi
__device__ __nv_bfloat16 g_zlo[NE];        // act(z2) bf16 lo
__device__ __nv_bfloat16 g_wwhi[384 * KCI];// tap-split conv1 weights, bf16 hi
__device__ __nv_bfloat16 g_wwlo[384 * KCI];// bf16 lo residual
__device__ __nv_bfloat16 g_w2hb[FILT * FILT];
__device__ __nv_bfloat16 g_w2lb[FILT * FILT];
__device__ float g_w1out[BB * C1 * FF];    // conv1 raw output (pre-BN)
__device__ float g_v[BB * FILT * FF];      // conv2 raw output (pre-BN)
__device__ float g_p1[2 * 64 * 1024];
__device__ float g_p2[2 * 64 * 3200];
__device__ float g_pC1[2 * 128 * 128];
__device__ float g_pC2[2 * 64 * 256];
__device__ float g_scale1[64], g_shift1[64];
__device__ float g_scale2[64], g_shift2[64];
__device__ float g_scaleC1[128], g_shiftC1[128];
__device__ float g_scaleC2[64], g_shiftC2[64];

__device__ __forceinline__ float dinvf(int j) {
    return (j == 0 || j == JJ - 1) ? 0.70710678118654752f : 0.57735026918962576f;
}
__device__ __forceinline__ float lrelu(float v) { return v >= 0.f ? v : 0.2f * v; }

#define MMA_BF16(d, av, b0, b1) \
    asm volatile("mma.sync.aligned.m16n8k16.row.col.f32.bf16.bf16.f32 " \
        "{%0,%1,%2,%3}, {%4,%5,%6,%7}, {%8,%9}, {%0,%1,%2,%3};" \
        : "+f"((d)[0]), "+f"((d)[1]), "+f"((d)[2]), "+f"((d)[3]) \
        : "r"((av)[0]), "r"((av)[1]), "r"((av)[2]), "r"((av)[3]), \
          "r"(b0), "r"(b1))

__device__ __forceinline__ void cp_async16(uint32_t saddr, const void* g) {
    asm volatile("cp.async.cg.shared.global [%0], [%1], 16;" :: "r"(saddr), "l"(g) : "memory");
}

// ---------------------------------------------------------------------------
// K0: merged prep + gcn1 stats.
// ---------------------------------------------------------------------------
__global__ __launch_bounds__(256) void prep_stats(
    const float* __restrict__ cw1, const float* __restrict__ W2,
    const float* __restrict__ x, const float* __restrict__ W1,
    const float* __restrict__ b1,
    __nv_bfloat16* __restrict__ whi, __nv_bfloat16* __restrict__ wlo,
    __nv_bfloat16* __restrict__ w2h, __nv_bfloat16* __restrict__ w2l,
    float* __restrict__ part) {
    int bid = blockIdx.x;
    int tid = threadIdx.x;
    if (bid < 2400) {
        int idx = bid * 256 + tid;                // < 614400 exactly
        int n = idx / KCI, ci = idx - n * KCI;
        int k = n >> 7, o = n & 127;
        float w = cw1[(size_t)o * 4800 + ci * 3 + k];
        __nv_bfloat16 hb = __float2bfloat16(w);
        whi[idx] = hb;
        wlo[idx] = __float2bfloat16(w - __bfloat162float(hb));
        return;
    }
    if (bid < 2416) {
        int i = (bid - 2400) * 256 + tid;         // < 4096
        int n = i >> 6, k = i & 63;
        float w = W2[k * 64 + n];
        __nv_bfloat16 hb = __float2bfloat16(w);
        w2h[i] = hb;
        w2l[i] = __float2bfloat16(w - __bfloat162float(hb));
        return;
    }
    int sb = bid - 2416;                          // 0..1023
    __shared__ float xs[1200], xef[1200], W1s[192], b1s[64], ss[256], qq[256];
    if (tid < 192) W1s[tid] = W1[tid];
    if (tid < 64) b1s[tid] = b1[tid];
    int base = sb * 1200;
    for (int i = tid; i < 1200; i += 256) xs[i] = x[base + i];
    __syncthreads();
    for (int i = tid; i < 400; i += 256) {
        int j = i % 25;
        float dj = dinvf(j);
        float cm = (j > 0) ? dinvf(j - 1) : 0.f;
        float cp = (j < 24) ? dinvf(j + 1) : 0.f;
        int im = (i > 0) ? i - 1 : 0, ip = (i < 399) ? i + 1 : 399;
#pragma unroll
        for (int d = 0; d < 3; d++)
            xef[i * 3 + d] = dj * (dj * xs[i * 3 + d] + cm * xs[im * 3 + d] + cp * xs[ip * 3 + d]);
    }
    __syncthreads();

    int c = tid & 63, sub = tid >> 6;
    float w0 = W1s[c], w1 = W1s[64 + c], w2 = W1s[128 + c], bb = b1s[c];
    float s = 0.f, q = 0.f;
    for (int it = 0; it < 100; it++) {
        int nl = it * 4 + sub;
        float z = xef[nl * 3] * w0 + xef[nl * 3 + 1] * w1 + xef[nl * 3 + 2] * w2 + bb;
        s += z; q += z * z;
    }
    ss[tid] = s; qq[tid] = q;
    __syncthreads();
    if (tid < 64) {
        s = ss[tid] + ss[tid + 64] + ss[tid + 128] + ss[tid + 192];
        q = qq[tid] + qq[tid + 64] + qq[tid + 128] + qq[tid + 192];
        part[tid * 1024 + sb] = s;
        part[65536 + tid * 1024 + sb] = q;
    }
}

// ---------------------------------------------------------------------------
// BN finalize: part layout S at [c*R + r], Q at [C*R + c*R + r].
// ---------------------------------------------------------------------------
__global__ __launch_bounds__(256) void bn_final(
    const float* __restrict__ part, int R, int C,
    const float* __restrict__ g, const float* __restrict__ be, float invN,
    float* __restrict__ scale, float* __restrict__ shift) {
    int c = blockIdx.x, tid = threadIdx.x;
    __shared__ float ss[256], qq[256];
    const float* pS = part + (size_t)c * R;
    const float* pQ = part + (size_t)C * R + (size_t)c * R;
    float s = 0.f, q = 0.f;
    for (int r = tid; r < R; r += 256) { s += pS[r]; q += pQ[r]; }
    ss[tid] = s; qq[tid] = q;
    __syncthreads();
    for (int o = 128; o > 0; o >>= 1) {
        if (tid < o) { ss[tid] += ss[tid + o]; qq[tid] += qq[tid + o]; }
        __syncthreads();
    }
    if (tid == 0) {
        float m = ss[0] * invN;
        float var = qq[0] * invN - m * m;
        float rstd = rsqrtf(var + EPSV);
        float sc = g[c] * rstd;
        scale[c] = sc;
        shift[c] = be[c] - m * sc;
    }
}

// ---------------------------------------------------------------------------
// K2: gcn2 via bf16x3 MMA.
// ---------------------------------------------------------------------------
#define G2S 72
#define G2_BYTES 55296

__global__ __launch_bounds__(256) void gcn2_mma(
    const float* __restrict__ x, const float* __restrict__ W1,
    const float* __restrict__ b1, const float* __restrict__ sc1,
    const float* __restrict__ sh1, const __nv_bfloat16* __restrict__ w2hb,
    const __nv_bfloat16* __restrict__ w2lb, const float* __restrict__ b2,
    float* __restrict__ part, float* __restrict__ z2b) {
    extern __shared__ __align__(16) char dynraw[];
    __nv_bfloat16* Ahi = reinterpret_cast<__nv_bfloat16*>(dynraw);
    __nv_bfloat16* Alo = reinterpret_cast<__nv_bfloat16*>(dynraw + 18432);
    __nv_bfloat16* Bhi = reinterpret_cast<__nv_bfloat16*>(dynraw + 36864);
    __nv_bfloat16* Blo = reinterpret_cast<__nv_bfloat16*>(dynraw + 46080);
    __shared__ __align__(16) float xs[396], xef[520];
    __shared__ __align__(16) float W1s[192], b1s[64], sc1s[64], sh1s[64], b2s[64];
    __shared__ float redS[256], redQ[256];

    int tid = threadIdx.x, lane = tid & 31, wid = tid >> 5;
    int n0 = blockIdx.x * 128;

    if (tid < 192) W1s[tid] = W1[tid];
    if (tid < 64) {
        b1s[tid] = b1[tid]; sc1s[tid] = sc1[tid];
        sh1s[tid] = sh1[tid]; b2s[tid] = b2[tid];
    }
    for (int i = tid; i < 396; i += 256) {
        int gi = (n0 - 2) * 3 + i;
        xs[i] = (gi >= 0 && gi < NNODES * 3) ? x[gi] : 0.f;
    }
    for (int i = tid; i < 2048; i += 256) {
        int n = i >> 5, kk = i & 31;
        *reinterpret_cast<uint32_t*>(Bhi + n * G2S + kk * 2) =
            *reinterpret_cast<const uint32_t*>(w2hb + n * 64 + kk * 2);
        *reinterpret_cast<uint32_t*>(Blo + n * G2S + kk * 2) =
            *reinterpret_cast<const uint32_t*>(w2lb + n * 64 + kk * 2);
    }
    __syncthreads();

    for (int i = tid; i < 130; i += 256) {
        int m = n0 - 1 + i;
        float e0 = 0.f, e1 = 0.f, e2 = 0.f;
        if (m >= 0 && m < NNODES) {
            int j = m % 25;
            float dj = dinvf(j);
            float cm = (j > 0) ? dinvf(j - 1) : 0.f;
            float cp = (j < 24) ? dinvf(j + 1) : 0.f;
            const float* xc = xs + (i + 1) * 3;
            e0 = dj * (dj * xc[0] + cm * xc[-3] + cp * xc[3]);
            e1 = dj * (dj * xc[1] + cm * xc[-2] + cp * xc[4]);
            e2 = dj * (dj * xc[2] + cm * xc[-1] + cp * xc[5]);
        }
        xef[i * 4] = e0; xef[i * 4 + 1] = e1; xef[i * 4 + 2] = e2;
    }
    __syncthreads();

    {
        const float4* W1s4 = reinterpret_cast<const float4*>(W1s);
        const float4* b4 = reinterpret_cast<const float4*>(b1s);
        const float4* sc4 = reinterpret_cast<const float4*>(sc1s);
        const float4* sh4 = reinterpret_cast<const float4*>(sh1s);
        for (int i = tid; i < 2048; i += 256) {
            int cg = i & 15, nl = i >> 4;
            int m = n0 + nl, j = m % 25;
            float dj = dinvf(j);
            float cm = (j > 0) ? dinvf(j - 1) : 0.f;
            float cp = (j < 24) ? dinvf(j + 1) : 0.f;
            float4 w0 = W1s4[cg], w1 = W1s4[16 + cg], w2 = W1s4[32 + cg];
            float4 bb = b4[cg], sv = sc4[cg], hs = sh4[cg];
            float4 h[3];
#pragma unroll
            for (int d = 0; d < 3; d++) {
                float e0 = xef[(nl + d) * 4], e1 = xef[(nl + d) * 4 + 1],
                      e2 = xef[(nl + d) * 4 + 2];
                float4 z;
                z.x = e0 * w0.x + e1 * w1.x + e2 * w2.x + bb.x;
                z.y = e0 * w0.y + e1 * w1.y + e2 * w2.y + bb.y;
                z.z = e0 * w0.z + e1 * w1.z + e2 * w2.z + bb.z;
                z.w = e0 * w0.w + e1 * w1.w + e2 * w2.w + bb.w;
                h[d].x = lrelu(fmaf(z.x, sv.x, hs.x));
                h[d].y = lrelu(fmaf(z.y, sv.y, hs.y));
                h[d].z = lrelu(fmaf(z.z, sv.z, hs.z));
                h[d].w = lrelu(fmaf(z.w, sv.w, hs.w));
            }
            float4 v;
            v.x = dj * (dj * h[1].x + cm * h[0].x + cp * h[2].x);
            v.y = dj * (dj * h[1].y + cm * h[0].y + cp * h[2].y);
            v.z = dj * (dj * h[1].z + cm * h[0].z + cp * h[2].z);
            v.w = dj * (dj * h[1].w + cm * h[0].w + cp * h[2].w);
            __nv_bfloat16 hx = __float2bfloat16(v.x), hy = __float2bfloat16(v.y);
            __nv_bfloat16 hz = __float2bfloat16(v.z), hw = __float2bfloat16(v.w);
            __nv_bfloat16 lx = __float2bfloat16(v.x - __bfloat162float(hx));
            __nv_bfloat16 ly = __float2bfloat16(v.y - __bfloat162float(hy));
            __nv_bfloat16 lz = __float2bfloat16(v.z - __bfloat162float(hz));
            __nv_bfloat16 lw = __float2bfloat16(v.w - __bfloat162float(hw));
            int di = nl * G2S + cg * 4;
            *reinterpret_cast<__nv_bfloat162*>(Ahi + di)     = __halves2bfloat162(hx, hy);
            *reinterpret_cast<__nv_bfloat162*>(Ahi + di + 2) = __halves2bfloat162(hz, hw);
            *reinterpret_cast<__nv_bfloat162*>(Alo + di)     = __halves2bfloat162(lx, ly);
            *reinterpret_cast<__nv_bfloat162*>(Alo + di + 2) = __halves2bfloat162(lz, lw);
        }
    }
    __syncthreads();

    int wm = wid & 3, wn = wid >> 2;
    float acc[2][4][4];
#pragma unroll
    for (int mt = 0; mt < 2; mt++)
#pragma unroll
        for (int nt = 0; nt < 4; nt++)
#pragma unroll
            for (int u = 0; u < 4; u++) acc[mt][nt][u] = 0.f;

#pragma unroll
    for (int kt = 0; kt < 4; kt++) {
        uint32_t ahi[2][4], alo[2][4], bhi[4][2], blo[4][2];
        int abase = (wm * 32 + (lane >> 2)) * G2S + (lane & 3) * 2 + kt * 16;
#pragma unroll
        for (int mt = 0; mt < 2; mt++) {
            int o = abase + mt * 16 * G2S;
            ahi[mt][0] = *reinterpret_cast<const uint32_t*>(Ahi + o);
            ahi[mt][1] = *reinterpret_cast<const uint32_t*>(Ahi + o + 8 * G2S);
            ahi[mt][2] = *reinterpret_cast<const uint32_t*>(Ahi + o + 8);
            ahi[mt][3] = *reinterpret_cast<const uint32_t*>(Ahi + o + 8 * G2S + 8);
            alo[mt][0] = *reinterpret_cast<const uint32_t*>(Alo + o);
            alo[mt][1] = *reinterpret_cast<const uint32_t*>(Alo + o + 8 * G2S);
            alo[mt][2] = *reinterpret_cast<const uint32_t*>(Alo + o + 8);
            alo[mt][3] = *reinterpret_cast<const uint32_t*>(Alo + o + 8 * G2S + 8);
        }
        int bbase = (wn * 32 + (lane >> 2)) * G2S + (lane & 3) * 2 + kt * 16;
#pragma unroll
        for (int nt = 0; nt < 4; nt++) {
            int o = bbase + nt * 8 * G2S;
            bhi[nt][0] = *reinterpret_cast<const uint32_t*>(Bhi + o);
            bhi[nt][1] = *reinterpret_cast<const uint32_t*>(Bhi + o + 8);
            blo[nt][0] = *reinterpret_cast<const uint32_t*>(Blo + o);
            blo[nt][1] = *reinterpret_cast<const uint32_t*>(Blo + o + 8);
        }
#pragma unroll
        for (int nt = 0; nt < 4; nt++) {
            MMA_BF16(acc[0][nt], ahi[0], bhi[nt][0], bhi[nt][1]);
            MMA_BF16(acc[1][nt], ahi[1], bhi[nt][0], bhi[nt][1]);
        }
#pragma unroll
        for (int nt = 0; nt < 4; nt++) {
            MMA_BF16(acc[0][nt], ahi[0], blo[nt][0], blo[nt][1]);
            MMA_BF16(acc[1][nt], ahi[1], blo[nt][0], blo[nt][1]);
        }
#pragma unroll
        for (int nt = 0; nt < 4; nt++) {
            MMA_BF16(acc[0][nt], alo[0], bhi[nt][0], bhi[nt][1]);
            MMA_BF16(acc[1][nt], alo[1], bhi[nt][0], bhi[nt][1]);
        }
    }

#pragma unroll
    for (int nt = 0; nt < 4; nt++) {
        int c0 = wn * 32 + nt * 8 + ((lane & 3) << 1);
        float bb0 = b2s[c0], bb1 = b2s[c0 + 1];
        float s0 = 0.f, q0 = 0.f, s1 = 0.f, q1 = 0.f;
#pragma unroll
        for (int mt = 0; mt < 2; mt++) {
            int row = n0 + wm * 32 + mt * 16 + (lane >> 2);
            float u0 = acc[mt][nt][0] + bb0, u1 = acc[mt][nt][1] + bb1;
            float u2 = acc[mt][nt][2] + bb0, u3 = acc[mt][nt][3] + bb1;
            *reinterpret_cast<float2*>(z2b + (size_t)row * 64 + c0) = make_float2(u0, u1);
            *reinterpret_cast<float2*>(z2b + (size_t)(row + 8) * 64 + c0) = make_float2(u2, u3);
            s0 += u0 + u2; q0 += u0 * u0 + u2 * u2;
            s1 += u1 + u3; q1 += u1 * u1 + u3 * u3;
        }
#pragma unroll
        for (int o = 4; o < 32; o <<= 1) {
            s0 += __shfl_xor_sync(0xffffffffu, s0, o);
            q0 += __shfl_xor_sync(0xffffffffu, q0, o);
            s1 += __shfl_xor_sync(0xffffffffu, s1, o);
            q1 += __shfl_xor_sync(0xffffffffu, q1, o);
        }
        if (lane < 4) {
            redS[c0 * 4 + wm] = s0; redS[(c0 + 1) * 4 + wm] = s1;
            redQ[c0 * 4 + wm] = q0; redQ[(c0 + 1) * 4 + wm] = q1;
        }
    }
    __syncthreads();
    if (tid < 64) {
        float S = redS[tid * 4] + redS[tid * 4 + 1] + redS[tid * 4 + 2] + redS[tid * 4 + 3];
        float Q = redQ[tid * 4] + redQ[tid * 4 + 1] + redQ[tid * 4 + 2] + redQ[tid * 4 + 3];
        part[tid * 3200 + blockIdx.x] = S;
        part[204800 + tid * 3200 + blockIdx.x] = Q;
    }
}

// ---------------------------------------------------------------------------
// K2b: z2 convert — BN2+LReLU+bf16 split.
// ---------------------------------------------------------------------------
__global__ __launch_bounds__(256) void z2convert(
    const float* __restrict__ z2, const float* __restrict__ sc,
    const float* __restrict__ sh, __nv_bfloat16* __restrict__ zhi,
    __nv_bfloat16* __restrict__ zlo) {
    __shared__ float scs[64], shs[64];
    int tid = threadIdx.x;
    if (tid < 64) { scs[tid] = sc[tid]; shs[tid] = sh[tid]; }
    __syncthreads();
    size_t base = (size_t)blockIdx.x * 1024 + tid * 4;
    int c = (tid * 4) & 63;
    float4 v = *reinterpret_cast<const float4*>(z2 + base);
    v.x = lrelu(fmaf(v.x, scs[c],     shs[c]));
    v.y = lrelu(fmaf(v.y, scs[c + 1], shs[c + 1]));
    v.z = lrelu(fmaf(v.z, scs[c + 2], shs[c + 2]));
    v.w = lrelu(fmaf(v.w, scs[c + 3], shs[c + 3]));
    __nv_bfloat16 hx = __float2bfloat16(v.x), hy = __float2bfloat16(v.y);
    __nv_bfloat16 hz = __float2bfloat16(v.z), hw = __float2bfloat16(v.w);
    __nv_bfloat16 lx = __float2bfloat16(v.x - __bfloat162float(hx));
    __nv_bfloat16 ly = __float2bfloat16(v.y - __bfloat162float(hy));
    __nv_bfloat16 lz = __float2bfloat16(v.z - __bfloat162float(hz));
    __nv_bfloat16 lw = __float2bfloat16(v.w - __bfloat162float(hw));
    *reinterpret_cast<__nv_bfloat162*>(zhi + base)     = __halves2bfloat162(hx, hy);
    *reinterpret_cast<__nv_bfloat162*>(zhi + base + 2) = __halves2bfloat162(hz, hw);
    *reinterpret_cast<__nv_bfloat162*>(zlo + base)     = __halves2bfloat162(lx, ly);
    *reinterpret_cast<__nv_bfloat162*>(zlo + base + 2) = __halves2bfloat162(lz, lw);
}

// ---------------------------------------------------------------------------
// K3: conv1 fused with shift-add.
// ---------------------------------------------------------------------------
#define AROWS 5200                                  // 130*40 bf16
#define BROWS 15360                                 // 384*40 bf16
#define STAGEE (2 * AROWS + 2 * BROWS)
#define CF_BYTES (2 * STAGEE * 2)                   // 164480

__global__ __launch_bounds__(256) void conv1_fused(
    const __nv_bfloat16* __restrict__ zhi, const __nv_bfloat16* __restrict__ zlo,
    const __nv_bfloat16* __restrict__ wwhi, const __nv_bfloat16* __restrict__ wwlo,
    const float* __restrict__ cb1, float* __restrict__ w1o,
    float* __restrict__ part) {
    extern __shared__ __align__(16) char dynraw[];
    __nv_bfloat16* sm = reinterpret_cast<__nv_bfloat16*>(dynraw);
    int tid = threadIdx.x, lane = tid & 31, wid = tid >> 5;
    int wm = wid & 3, wn = wid >> 2;
    int m0 = blockIdx.x * 128;
    int bidx = m0 >> 8;
    int f0g = m0 & 255;
    int zr = (f0g == 0) ? 0 : 129;
    int mA0 = m0 - 1;

    float acc[2][8][4];
#pragma unroll
    for (int mt = 0; mt < 2; mt++)
#pragma unroll
        for (int nt = 0; nt < 8; nt++)
#pragma unroll
            for (int u = 0; u < 4; u++) acc[mt][nt][u] = 0.f;

#define LOADAB(bufi, step) do { \
        int ci0_ = (step) * 32; \
        __nv_bfloat16* Ah_ = sm + (bufi) * STAGEE; \
        __nv_bfloat16* Al_ = Ah_ + AROWS; \
        __nv_bfloat16* Bh_ = Al_ + AROWS; \
        __nv_bfloat16* Bl_ = Bh_ + BROWS; \
        if (tid < 16) { \
            __nv_bfloat16* zd = (tid < 8 ? Ah_ : Al_) + zr * 40 + (tid & 7) * 4; \
            *reinterpret_cast<float2*>(zd) = make_float2(0.f, 0.f); \
        } \
        _Pragma("unroll") \
        for (int u = 0; u < 5; u++) { \
            int fi = u * 256 + tid; \
            if (fi < 1040) { \
                int sel = fi >= 520; \
                int rem = sel ? fi - 520 : fi; \
                int row = rem >> 2, gg = rem & 3; \
                if (row != zr) { \
                    const __nv_bfloat16* src = (sel ? zlo : zhi) + \
                        (size_t)(mA0 + row) * KCI + ci0_ + gg * 8; \
                    __nv_bfloat16* dst = (sel ? Al_ : Ah_) + row * 40 + gg * 8; \
                    cp_async16((uint32_t)__cvta_generic_to_shared(dst), src); \
                } \
            } \
        } \
        _Pragma("unroll") \
        for (int u = 0; u < 12; u++) { \
            int fi = u * 256 + tid; \
            int sel = fi >= 1536; \
            int rem = sel ? fi - 1536 : fi; \
            int row = rem >> 2, gg = rem & 3; \
            const __nv_bfloat16* src = (sel ? wwlo : wwhi) + \
                (size_t)row * KCI + ci0_ + gg * 8; \
            __nv_bfloat16* dst = (sel ? Bl_ : Bh_) + row * 40 + gg * 8; \
            cp_async16((uint32_t)__cvta_generic_to_shared(dst), src); \
        } \
        asm volatile("cp.async.commit_group;" ::: "memory"); \
    } while (0)

    LOADAB(0, 0);

    for (int i = 0; i < 50; i++) {
        int buf = i & 1;
        asm volatile("cp.async.wait_group 0;" ::: "memory");
        __syncthreads();
        if (i < 49) LOADAB(buf ^ 1, i + 1);

        const __nv_bfloat16* Ah = sm + buf * STAGEE;
        const __nv_bfloat16* Al = Ah + AROWS;
        const __nv_bfloat16* Bh = Al + AROWS;
        const __nv_bfloat16* Bl = Bh + BROWS;
#pragma unroll
        for (int kt = 0; kt < 2; kt++) {
#pragma unroll
            for (int tap = 0; tap < 3; tap++) {
                uint32_t ahi[2][4], alo[2][4], bhi[8][2], blo[8][2];
                int abase = (wm * 32 + tap + (lane >> 2)) * 40 + (lane & 3) * 2 + kt * 16;
#pragma unroll
                for (int mt = 0; mt < 2; mt++) {
                    int o = abase + mt * 640;
                    ahi[mt][0] = *reinterpret_cast<const uint32_t*>(Ah + o);
                    ahi[mt][1] = *reinterpret_cast<const uint32_t*>(Ah + o + 320);
                    ahi[mt][2] = *reinterpret_cast<const uint32_t*>(Ah + o + 8);
                    ahi[mt][3] = *reinterpret_cast<const uint32_t*>(Ah + o + 328);
                    alo[mt][0] = *reinterpret_cast<const uint32_t*>(Al + o);
                    alo[mt][1] = *reinterpret_cast<const uint32_t*>(Al + o + 320);
                    alo[mt][2] = *reinterpret_cast<const uint32_t*>(Al + o + 8);
                    alo[mt][3] = *reinterpret_cast<const uint32_t*>(Al + o + 328);
                }
                int bbase = (tap * 128 + wn * 64 + (lane >> 2)) * 40 + (lane & 3) * 2 + kt * 16;
#pragma unroll
                for (int nt = 0; nt < 8; nt++) {
                    int o = bbase + nt * 320;
                    bhi[nt][0] = *reinterpret_cast<const uint32_t*>(Bh + o);
                    bhi[nt][1] = *reinterpret_cast<const uint32_t*>(Bh + o + 8);
                    blo[nt][0] = *reinterpret_cast<const uint32_t*>(Bl + o);
                    blo[nt][1] = *reinterpret_cast<const uint32_t*>(Bl + o + 8);
                }
#pragma unroll
                for (int nt = 0; nt < 8; nt++) {
                    MMA_BF16(acc[0][nt], ahi[0], bhi[nt][0], bhi[nt][1]);
                    MMA_BF16(acc[1][nt], ahi[1], bhi[nt][0], bhi[nt][1]);
                }
#pragma unroll
                for (int nt = 0; nt < 8; nt++) {
                    MMA_BF16(acc[0][nt], ahi[0], blo[nt][0], blo[nt][1]);
                    MMA_BF16(acc[1][nt], ahi[1], blo[nt][0], blo[nt][1]);
                }
#pragma unroll
                for (int nt = 0; nt < 8; nt++) {
                    MMA_BF16(acc[0][nt], alo[0], bhi[nt][0], bhi[nt][1]);
                    MMA_BF16(acc[1][nt], alo[1], bhi[nt][0], bhi[nt][1]);
                }
            }
        }
    }

    __syncthreads();
    float* T = reinterpret_cast<float*>(sm);         // 128 x 132
#pragma unroll
    for (int mt = 0; mt < 2; mt++)
#pragma unroll
        for (int nt = 0; nt < 8; nt++)
#pragma unroll
            for (int u = 0; u < 4; u++) {
                int fo = wm * 32 + mt * 16 + (lane >> 2) + ((u >> 1) ? 8 : 0);
                int o = wn * 64 + nt * 8 + ((lane & 3) << 1) + (u & 1);
                T[o * 132 + fo] = acc[mt][nt][u] + __ldg(cb1 + o);
            }
    __syncthreads();
    for (int i = tid; i < 4096; i += 256) {
        int o = i >> 5, f4 = i & 31;
        float4 v = *reinterpret_cast<const float4*>(T + o * 132 + f4 * 4);
        *reinterpret_cast<float4*>(
            w1o + (size_t)(bidx * 128 + o) * 256 + f0g + f4 * 4) = v;
    }
    if (tid < 128) {
        float S = 0.f, Q = 0.f;
#pragma unroll 8
        for (int k = 0; k < 128; k++) {
            float v = T[tid * 132 + k];
            S += v; Q += v * v;
        }
        part[tid * 128 + blockIdx.x] = S;
        part[16384 + tid * 128 + blockIdx.x] = Q;
    }
#undef LOADAB
}

// ---------------------------------------------------------------------------
// K6: Conv2 (1x1, 128->64) with bnC1+lrelu fused at load + partial stats.
// ---------------------------------------------------------------------------
__global__ __launch_bounds__(256) void conv2_kernel(
    const float* __restrict__ w1o, const float* __restrict__ cw2,
    const float* __restrict__ cb2, const float* __restrict__ sc,
    const float* __restrict__ sh, float* __restrict__ vout,
    float* __restrict__ part) {
    __shared__ __align__(16) float Us[64 * 64];
    __shared__ __align__(16) float Ws2[64 * 64];
    int tid = threadIdx.x;
    int b = blockIdx.y;
    int f0 = blockIdx.x * 64;
    int fth = tid & 15, oth = tid >> 4;
    float acc[4][4] = {};

    for (int ci0 = 0; ci0 < 128; ci0 += 64) {
        for (int i = tid; i < 4096; i += 256) {
            int cc = i >> 6, ffi = i & 63;
            float raw = w1o[(size_t)(b * 128 + ci0 + cc) * 256 + f0 + ffi];
            float v = fmaf(raw, __ldg(sc + ci0 + cc), __ldg(sh + ci0 + cc));
            Us[i] = lrelu(v);
        }
        for (int i = tid; i < 4096; i += 256) {
            int o = i & 63, cc = i >> 6;
            Ws2[cc * 64 + o] = cw2[o * 128 + ci0 + cc];
        }
        __syncthreads();
#pragma unroll 8
        for (int cc = 0; cc < 64; cc++) {
            float4 iv = *reinterpret_cast<const float4*>(Us + cc * 64 + fth * 4);
            float4 wv = *reinterpret_cast<const float4*>(Ws2 + cc * 64 + oth * 4);
            acc[0][0] = fmaf(wv.x, iv.x, acc[0][0]); acc[0][1] = fmaf(wv.x, iv.y, acc[0][1]);
            acc[0][2] = fmaf(wv.x, iv.z, acc[0][2]); acc[0][3] = fmaf(wv.x, iv.w, acc[0][3]);
            acc[1][0] = fmaf(wv.y, iv.x, acc[1][0]); acc[1][1] = fmaf(wv.y, iv.y, acc[1][1]);
            acc[1][2] = fmaf(wv.y, iv.z, acc[1][2]); acc[1][3] = fmaf(wv.y, iv.w, acc[1][3]);
            acc[2][0] = fmaf(wv.z, iv.x, acc[2][0]); acc[2][1] = fmaf(wv.z, iv.y, acc[2][1]);
            acc[2][2] = fmaf(wv.z, iv.z, acc[2][2]); acc[2][3] = fmaf(wv.z, iv.w, acc[2][3]);
            acc[3][0] = fmaf(wv.w, iv.x, acc[3][0]); acc[3][1] = fmaf(wv.w, iv.y, acc[3][1]);
            acc[3][2] = fmaf(wv.w, iv.z, acc[3][2]); acc[3][3] = fmaf(wv.w, iv.w, acc[3][3]);
        }
        __syncthreads();
    }

    float* reds = Us;
    float* redq = Ws2;
#pragma unroll
    for (int i = 0; i < 4; i++) {
        int o = oth * 4 + i;
        float bias = __ldg(cb2 + o);
        float s = 0.f, q = 0.f;
#pragma unroll
        for (int j2 = 0; j2 < 4; j2++) {
            float r = acc[i][j2] + bias;
            vout[(size_t)(b * 64 + o) * 256 + f0 + fth * 4 + j2] = r;
            s += r; q += r * r;
        }
        reds[o * 17 + fth] = s;
        redq[o * 17 + fth] = q;
    }
    __syncthreads();
    if (tid < 64) {
        float S = 0.f, Q = 0.f;
#pragma unroll
        for (int t = 0; t < 16; t++) { S += reds[tid * 17 + t]; Q += redq[tid * 17 + t]; }
        int blk = blockIdx.y * 4 + blockIdx.x;
        part[tid * 256 + blk] = S;
        part[16384 + tid * 256 + blk] = Q;
    }
}

// ---------------------------------------------------------------------------
// K7: final BN + LReLU + transpose (B,64,256) -> (B,256,64)
// ---------------------------------------------------------------------------
__global__ __launch_bounds__(256) void final_kernel(
    const float* __restrict__ v, const float* __restrict__ sc,
    const float* __restrict__ sh, float* __restrict__ out) {
    __shared__ float s[64 * 65];
    int tid = threadIdx.x;
    int b = blockIdx.y;
    int f0 = blockIdx.x * 64;
    for (int i = tid; i < 4096; i += 256) {
        int o = i >> 6, ffi = i & 63;
        s[o * 65 + ffi] = v[(size_t)(b * 64 + o) * 256 + f0 + ffi];
    }
    __syncthreads();
    for (int i = tid; i < 4096; i += 256) {
        int ffi = i >> 6, o = i & 63;
        float val = fmaf(s[o * 65 + ffi], __ldg(sc + o), __ldg(sh + o));
        out[(size_t)(b * 256 + f0 + ffi) * 64 + o] = lrelu(val);
    }
}

// ---------------------------------------------------------------------------
// Launch
// ---------------------------------------------------------------------------
extern "C" void kernel_launch(void* const* d_in, const int* in_sizes, int n_in,
                              void* d_out, int out_size) {
    const float* x   = (const float*)d_in[0];
    const float* W1  = (const float*)d_in[4];
    const float* b1  = (const float*)d_in[5];
    const float* g1  = (const float*)d_in[6];
    const float* be1 = (const float*)d_in[7];
    const float* W2  = (const float*)d_in[8];
    const float* b2  = (const float*)d_in[9];
    const float* g2  = (const float*)d_in[10];
    const float* be2 = (const float*)d_in[11];
    const float* cw1 = (const float*)d_in[12];
    const float* cb1 = (const float*)d_in[13];
    const float* cg1 = (const float*)d_in[14];
    const float* cbe1= (const float*)d_in[15];
    const float* cw2 = (const float*)d_in[16];
    const float* cb2 = (const float*)d_in[17];
    const float* cg2 = (const float*)d_in[18];
    const float* cbe2= (const float*)d_in[19];
    float* out = (float*)d_out;

    float *z2, *w1o, *v, *p1, *p2, *pC1, *pC2;
    __nv_bfloat16 *zhi, *zlo, *whi, *wlo, *w2h, *w2l;
    float *s1, *h1, *s2, *h2, *sC1, *hC1, *sC2, *hC2;
    cudaGetSymbolAddress((void**)&z2,  g_z2);
    cudaGetSymbolAddress((void**)&zhi, g_zhi);
    cudaGetSymbolAddress((void**)&zlo, g_zlo);
    cudaGetSymbolAddress((void**)&whi, g_wwhi);
    cudaGetSymbolAddress((void**)&wlo, g_wwlo);
    cudaGetSymbolAddress((void**)&w2h, g_w2hb);
    cudaGetSymbolAddress((void**)&w2l, g_w2lb);
    cudaGetSymbolAddress((void**)&w1o, g_w1out);
    cudaGetSymbolAddress((void**)&v,   g_v);
    cudaGetSymbolAddress((void**)&p1,  g_p1);
    cudaGetSymbolAddress((void**)&p2,  g_p2);
    cudaGetSymbolAddress((void**)&pC1, g_pC1);
    cudaGetSymbolAddress((void**)&pC2, g_pC2);
    cudaGetSymbolAddress((void**)&s1,  g_scale1);
    cudaGetSymbolAddress((void**)&h1,  g_shift1);
    cudaGetSymbolAddress((void**)&s2,  g_scale2);
    cudaGetSymbolAddress((void**)&h2,  g_shift2);
    cudaGetSymbolAddress((void**)&sC1, g_scaleC1);
    cudaGetSymbolAddress((void**)&hC1, g_shiftC1);
    cudaGetSymbolAddress((void**)&sC2, g_scaleC2);
    cudaGetSymbolAddress((void**)&hC2, g_shiftC2);

    cudaFuncSetAttribute(conv1_fused, cudaFuncAttributeMaxDynamicSharedMemorySize, CF_BYTES);
    cudaFuncSetAttribute(gcn2_mma,   cudaFuncAttributeMaxDynamicSharedMemorySize, G2_BYTES);

    const float invN_nodes = 1.f / (float)NNODES;
    const float invN_bf    = 1.f / (float)(BB * FF);

    prep_stats<<<3440, 256>>>(cw1, W2, x, W1, b1, whi, wlo, w2h, w2l, p1);     // 0
    bn_final<<<64, 256>>>(p1, 1024, 64, g1, be1, invN_nodes, s1, h1);          // 1
    gcn2_mma<<<3200, 256, G2_BYTES>>>(x, W1, b1, s1, h1, w2h, w2l, b2, p2, z2);// 2
    bn_final<<<64, 256>>>(p2, 3200, 64, g2, be2, invN_nodes, s2, h2);          // 3
    z2convert<<<25600, 256>>>(z2, s2, h2, zhi, zlo);                           // 4
    conv1_fused<<<128, 256, CF_BYTES>>>(zhi, zlo, whi, wlo, cb1, w1o, pC1);    // 5
    bn_final<<<128, 256>>>(pC1, 128, 128, cg1, cbe1, invN_bf, sC1, hC1);       // 6
    conv2_kernel<<<dim3(4, BB), 256>>>(w1o, cw2, cb2, sC1, hC1, v, pC2);       // 7
    bn_final<<<64, 256>>>(pC2, 256, 64, cg2, cbe2, invN_bf, sC2, hC2);         // 8
    final_kernel<<<dim3(4, BB), 256>>>(v, sC2, hC2, out);                      // 9
}